// round 12
// baseline (speedup 1.0000x reference)
#include <cuda_runtime.h>
#include <math.h>

#define BB   8
#define NN   512
#define DD   128
#define HH   64
#define FNN  3
#define BN   4096
#define MAXDEG 192

// ---------------- device scratch ----------------
__device__ float  g_wm1;
__device__ float  g_kap[BN];
__device__ float4 g_fp[BN];          // f0,f1,f2 packed
__device__ int    g_rank[BN];
__device__ int    g_cnt[BN];
__device__ int    g_adj[BN][MAXDEG];
__device__ float  g_af[FNN][BN];
__device__ float4 g_gdf[BN * 3];     // per node, per i: (gamma, df, fdf, -)
__device__ float  g_term[BN];
__device__ float  g_h[3][BN * HH];
__device__ float  g_za[BN * HH];
__device__ float  g_zb[BN * HH];
__device__ float  g_part[128 * 320];

// packed dual-fp32 FMA (sm_103a FFMA2)
__device__ __forceinline__ float2 ffma2(float2 a, float2 b, float2 c) {
    union U { float2 f; unsigned long long u; } ua, ub, uc, ud;
    ua.f = a; ub.f = b; uc.f = c;
    asm("fma.rn.f32x2 %0, %1, %2, %3;" : "=l"(ud.u) : "l"(ua.u), "l"(ub.u), "l"(uc.u));
    return ud.f;
}

// ================= K1: adj (0..1023) + node MLPs per-m (1024..1663) + wm1 (1664) =================
__global__ __launch_bounds__(256) void k_pre(
        const float* __restrict__ A, const float* __restrict__ X,
        const float* __restrict__ cW1, const float* __restrict__ cb1,
        const float* __restrict__ cW2, const float* __restrict__ cb2,
        const float* __restrict__ fW1, const float* __restrict__ fb1,
        const float* __restrict__ fW2, const float* __restrict__ fb2,
        const float* __restrict__ z0W1,
        const float* __restrict__ wW1, const float* __restrict__ wb1,
        const float* __restrict__ wW2, const float* __restrict__ wb2,
        const float* __restrict__ wW3, const float* __restrict__ wb3) {
    extern __shared__ float sm[];
    int t = threadIdx.x;
    if (blockIdx.x < 1024) {            // ---- CSR build: 4 rows/block
        int rs = t >> 6;
        int row = blockIdx.x * 4 + rs;
        int tt = t & 63;
        int lane = t & 31;
        int wr = (t >> 5) & 1;
        const float4* A4 = (const float4*)(A + (size_t)row * 512);
        float4 v0 = A4[tt * 2];
        float4 v1 = A4[tt * 2 + 1];
        unsigned flags = (v0.x != 0.f ?   1u : 0u) | (v0.y != 0.f ?   2u : 0u) |
                         (v0.z != 0.f ?   4u : 0u) | (v0.w != 0.f ?   8u : 0u) |
                         (v1.x != 0.f ?  16u : 0u) | (v1.y != 0.f ?  32u : 0u) |
                         (v1.z != 0.f ?  64u : 0u) | (v1.w != 0.f ? 128u : 0u);
        int c = __popc(flags);
        int sc = c;
        #pragma unroll
        for (int o = 1; o < 32; o <<= 1) {
            int n = __shfl_up_sync(0xffffffffu, sc, o);
            if (lane >= o) sc += n;
        }
        __shared__ int wsum[4][2];
        if (lane == 31) wsum[rs][wr] = sc;
        __syncthreads();
        int off = ((wr == 1) ? wsum[rs][0] : 0) + sc - c;
        int col = tt * 8;
        #pragma unroll
        for (int k = 0; k < 8; k++) {
            if ((flags >> k) & 1u) {
                if (off < MAXDEG) g_adj[row][off] = col + k;
                off++;
            }
        }
        if (tt == 63) g_cnt[row] = wsum[rs][0] + wsum[rs][1];
        return;
    }
    if (blockIdx.x == 1664) {           // ---- wm1
        __shared__ float h1[64], h2[32];
        if (t < 64) h1[t] = fmaxf(wW1[t] + wb1[t], 0.f);
        __syncthreads();
        if (t < 32) {
            float s = wb2[t];
            for (int k = 0; k < 64; k++) s = fmaf(h1[k], wW2[k * 32 + t], s);
            h2[t] = fmaxf(s, 0.f);
        }
        __syncthreads();
        if (t == 0) {
            float s = wb3[0];
            for (int k = 0; k < 32; k++) s = fmaf(h2[k], wW3[k], s);
            g_wm1 = 1.f / (1.f + expf(-s));
        }
        return;
    }
    // ---- node MLP: one (m, tile) per block
    int mb = blockIdx.x - 1024;
    int m = mb >> 7;
    int tile = mb & 127;
    float* sW = sm;
    float* xT = sW + 128 * 64;
    float* sP = xT + 128 * 36;
    int row0 = tile * 32;
    const float* W1 = (m == 0) ? cW1 : (m < 4 ? fW1 + (m - 1) * 8192 : z0W1);
    for (int i = t; i < 2048; i += 256) ((float4*)sW)[i] = ((const float4*)W1)[i];
    #pragma unroll
    for (int k = 0; k < 4; k++) {
        int i = t + k * 256;
        float4 v = ((const float4*)(X + (size_t)row0 * 128))[i];
        int li = i * 4;
        int r = li >> 7, d = li & 127;
        xT[(d + 0) * 36 + r] = v.x;
        xT[(d + 1) * 36 + r] = v.y;
        xT[(d + 2) * 36 + r] = v.z;
        xT[(d + 3) * 36 + r] = v.w;
    }
    __syncthreads();
    int hp = t & 31, rq = t >> 5;
    float2 a00 = make_float2(0.f, 0.f), a01 = a00, a10 = a00, a11 = a00;
    #pragma unroll 4
    for (int d = 0; d < 128; d++) {
        float2 wv = *(const float2*)&sW[d * 64 + hp * 2];
        float4 xv = *(const float4*)&xT[d * 36 + rq * 4];
        float2 x01 = make_float2(xv.x, xv.y), x23 = make_float2(xv.z, xv.w);
        float2 w0 = make_float2(wv.x, wv.x), w1 = make_float2(wv.y, wv.y);
        a00 = ffma2(x01, w0, a00); a01 = ffma2(x23, w0, a01);
        a10 = ffma2(x01, w1, a10); a11 = ffma2(x23, w1, a11);
    }
    int rb = rq * 4;
    if (m < 4) {
        const float* b1 = (m == 0) ? cb1 : fb1 + (m - 1) * 64;
        const float* W2 = (m == 0) ? cW2 : fW2 + (m - 1) * 64;
        float b10 = b1[hp * 2], b11 = b1[hp * 2 + 1];
        float w20 = W2[hp * 2], w21 = W2[hp * 2 + 1];
        sP[(rb + 0) * 33 + hp] = fmaxf(a00.x + b10, 0.f) * w20 + fmaxf(a10.x + b11, 0.f) * w21;
        sP[(rb + 1) * 33 + hp] = fmaxf(a00.y + b10, 0.f) * w20 + fmaxf(a10.y + b11, 0.f) * w21;
        sP[(rb + 2) * 33 + hp] = fmaxf(a01.x + b10, 0.f) * w20 + fmaxf(a11.x + b11, 0.f) * w21;
        sP[(rb + 3) * 33 + hp] = fmaxf(a01.y + b10, 0.f) * w20 + fmaxf(a11.y + b11, 0.f) * w21;
        __syncthreads();
        if (t < 32) {
            float s = (m == 0) ? cb2[0] : fb2[m - 1];
            const float* pr = &sP[t * 33];
            #pragma unroll
            for (int k = 0; k < 32; k++) s += pr[k];
            float v = 1.f / (1.f + expf(-s));
            if (m == 0) g_kap[row0 + t] = v;
            else ((float*)&g_fp[row0 + t])[m - 1] = v;
        }
    } else {                            // z0 = X @ g0W1
        *(float2*)&g_za[(size_t)(row0 + rb + 0) * 64 + hp * 2] = make_float2(a00.x, a10.x);
        *(float2*)&g_za[(size_t)(row0 + rb + 1) * 64 + hp * 2] = make_float2(a00.y, a10.y);
        *(float2*)&g_za[(size_t)(row0 + rb + 2) * 64 + hp * 2] = make_float2(a01.x, a11.x);
        *(float2*)&g_za[(size_t)(row0 + rb + 3) * 64 + hp * 2] = make_float2(a01.y, a11.y);
    }
}

// ================= helpers (512-thread kernels) =================
__device__ __forceinline__ void spmv1_block(int blk) {
    int row = blk * 16 + (threadIdx.x >> 5);
    int lane = threadIdx.x & 31;
    int base = row & ~511;
    int cnt = min(g_cnt[row], MAXDEG);
    float af[FNN] = {0, 0, 0}, aq[FNN] = {0, 0, 0};
    for (int n = lane; n < cnt; n += 32) {
        int gc = base + g_adj[row][n];
        float4 fv = g_fp[gc];
        af[0] += fv.x; aq[0] += fv.x * fv.x;
        af[1] += fv.y; aq[1] += fv.y * fv.y;
        af[2] += fv.z; aq[2] += fv.z * fv.z;
    }
    #pragma unroll
    for (int i = 0; i < FNN; i++) {
        #pragma unroll
        for (int o = 16; o > 0; o >>= 1) {
            af[i] += __shfl_down_sync(0xffffffffu, af[i], o);
            aq[i] += __shfl_down_sync(0xffffffffu, aq[i], o);
        }
    }
    if (lane == 0) {
        float w1 = g_wm1;
        float degw = w1 * (float)cnt;
        float4 fr = g_fp[row];
        const float fa[3] = {fr.x, fr.y, fr.z};
        #pragma unroll
        for (int i = 0; i < FNN; i++) {
            float f = fa[i];
            float wf = w1 * af[i];
            float gamma = 0.5f * (f * f * degw - 2.f * f * wf + w1 * aq[i]);
            float df = f * degw - wf;
            g_af[i][row] = af[i];
            g_gdf[row * 3 + i] = make_float4(gamma, df, f * df, 0.f);
        }
    }
}

__device__ __forceinline__ void spmv2_block(int blk) {
    int row = blk * 16 + (threadIdx.x >> 5);
    int lane = threadIdx.x & 31;
    int base = row & ~511;
    int cnt = min(g_cnt[row], MAXDEG);
    float ag[FNN] = {0, 0, 0}, ad[FNN] = {0, 0, 0}, afd[FNN] = {0, 0, 0};
    for (int n = lane; n < cnt; n += 32) {
        int gc = base + g_adj[row][n];
        #pragma unroll
        for (int i = 0; i < FNN; i++) {
            float4 v = g_gdf[gc * 3 + i];
            ag[i] += v.x; ad[i] += v.y; afd[i] += v.z;
        }
    }
    #pragma unroll
    for (int i = 0; i < FNN; i++) {
        #pragma unroll
        for (int o = 16; o > 0; o >>= 1) {
            ag[i]  += __shfl_down_sync(0xffffffffu, ag[i], o);
            ad[i]  += __shfl_down_sync(0xffffffffu, ad[i], o);
            afd[i] += __shfl_down_sync(0xffffffffu, afd[i], o);
        }
    }
    if (lane == 0) {
        float w1 = g_wm1;
        float kap = g_kap[row];
        float degw = w1 * (float)cnt;
        float term = -3.f * kap;
        float4 fr = g_fp[row];
        const float fa[3] = {fr.x, fr.y, fr.z};
        #pragma unroll
        for (int i = 0; i < FNN; i++) {
            float4 gv = g_gdf[row * 3 + i];
            float f = fa[i];
            float gamma = gv.x, df = gv.y;
            float wf = w1 * g_af[i][row];
            float dgamma = gamma * degw - w1 * ag[i];
            float gfd = 0.5f * (f * df * degw - f * w1 * ad[i]
                                - df * wf + w1 * afd[i]);
            float gamma2 = 0.5f * dgamma - gfd;
            term += fmaxf(kap * gamma - gamma2, 0.f);
        }
        g_term[row] = term;
    }
}

__device__ __forceinline__ void rank_block(int b, float* sv) {
    int t = threadIdx.x;
    sv[t] = g_kap[b * 512 + t];
    __syncthreads();
    float vi = sv[t];
    int c = 0;
    #pragma unroll 8
    for (int j = 0; j < 512; j++) {
        float vj = sv[j];
        c += (vj > vi) || (vj == vi && j < t);
    }
    g_rank[b * 512 + t] = c;
}

// ---- GIN: 8 rows/block, 512 threads; 2 warps/row split the NEIGHBOR list, float2 loads ----
__device__ __forceinline__ void gin_block512(int blk, const float* __restrict__ zin,
                                             float c1, int cut,
                                             const float* __restrict__ b1,
                                             const float* __restrict__ W2, const float* __restrict__ b2,
                                             const float* __restrict__ W1n,
                                             float* __restrict__ hout, float* __restrict__ znext,
                                             float* sm) {
    float* sW2  = sm;                       // 64*64
    float* sW1n = sW2 + 4096;               // 64*64
    int*   sidx = (int*)(sW1n + 4096);      // 8*192
    int*   sm_m = sidx + 8 * MAXDEG;        // 8
    float* sPa  = (float*)(sm_m + 8);       // 8*66 partial (half 0)
    float* sPb  = sPa + 8 * 66;             // 8*66 partial (half 1)
    float* sU   = sPb + 8 * 66;             // 8*68
    float* sH   = sU + 8 * 68;              // 8*68
    int t = threadIdx.x;
    int wr = t >> 5, lane = t & 31;
    int row0 = blk * 8;
    if (wr >= 8) {                          // warps 8..15: stage weights
        int tt = t - 256;
        for (int i = tt; i < 1024; i += 256) ((float4*)sW2)[i] = ((const float4*)W2)[i];
        if (W1n) for (int i = tt; i < 1024; i += 256) ((float4*)sW1n)[i] = ((const float4*)W1n)[i];
    } else {                                // warps 0..7: masked neighbor compaction
        int row = row0 + wr;
        int base = row & ~511;
        int cnt = min(g_cnt[row], MAXDEG);
        int m = 0;
        int* si = sidx + wr * MAXDEG;
        if (cut == 0) {
            for (int n = lane; n < cnt; n += 32) si[n] = base + g_adj[row][n];
            m = cnt;
        } else if (g_rank[row] >= cut) {
            for (int n0 = 0; n0 < cnt; n0 += 32) {
                int n = n0 + lane;
                int gc = 0; bool v = false;
                if (n < cnt) { gc = base + g_adj[row][n]; v = g_rank[gc] >= cut; }
                unsigned bm = __ballot_sync(0xffffffffu, v);
                if (v) si[m + __popc(bm & ((1u << lane) - 1u))] = gc;
                m += __popc(bm);
            }
        }
        if (lane == 0) sm_m[wr] = m;
    }
    __syncthreads();
    // gather: warp (r, half) sums its HALF of the neighbor list across all 64 dims (float2/lane)
    int r = wr & 7;
    int half = wr >> 3;
    {
        int m = sm_m[r];
        int s0 = half ? ((m + 1) >> 1) : 0;
        int e0 = half ? m : ((m + 1) >> 1);
        const int* si = sidx + r * MAXDEG;
        float2 a = make_float2(0.f, 0.f);
        int n = s0;
        for (; n + 4 <= e0; n += 4) {
            float2 v0 = *(const float2*)&zin[(size_t)si[n + 0] * 64 + lane * 2];
            float2 v1 = *(const float2*)&zin[(size_t)si[n + 1] * 64 + lane * 2];
            float2 v2 = *(const float2*)&zin[(size_t)si[n + 2] * 64 + lane * 2];
            float2 v3 = *(const float2*)&zin[(size_t)si[n + 3] * 64 + lane * 2];
            a.x += (v0.x + v1.x) + (v2.x + v3.x);
            a.y += (v0.y + v1.y) + (v2.y + v3.y);
        }
        for (; n < e0; n++) {
            float2 v = *(const float2*)&zin[(size_t)si[n] * 64 + lane * 2];
            a.x += v.x; a.y += v.y;
        }
        float* dst = half ? sPb : sPa;
        *(float2*)&dst[r * 66 + lane * 2] = a;
    }
    __syncthreads();
    // combine: warp (r, half) computes u for dims [32*half, 32*half+32)
    {
        int row = row0 + r;
        int d = lane + 32 * half;
        float zv = zin[(size_t)row * 64 + d];
        float s = sPa[r * 66 + d] + sPb[r * 66 + d];
        sU[r * 68 + d] = fmaxf(fmaf(c1, zv, s) + b1[d], 0.f);
    }
    __syncthreads();
    // layer 2: h = relu(u @ W2 + b2)
    int row = row0 + r;
    int hid = lane + 32 * half;
    {
        const float* ur = sU + r * 68;
        float acc = 0.f;
        #pragma unroll 16
        for (int k = 0; k < 64; k++) acc = fmaf(ur[k], sW2[k * 64 + hid], acc);
        float hv = fmaxf(acc + b2[hid], 0.f);
        hout[(size_t)row * 64 + hid] = hv;
        if (W1n) sH[r * 68 + hid] = hv;
    }
    if (!W1n) return;
    __syncthreads();
    {   // znext = h @ W1n
        const float* hr = sH + r * 68;
        float acc = 0.f;
        #pragma unroll 16
        for (int k = 0; k < 64; k++) acc = fmaf(hr[k], sW1n[k * 64 + hid], acc);
        znext[(size_t)row * 64 + hid] = acc;
    }
}

// ================= K2: spmv1 (0..255) + rank (256..263) + gin0 (264..775) =================
__global__ __launch_bounds__(512) void k_mid1(
        const float* __restrict__ eps, const int* __restrict__ p,
        const float* __restrict__ b1, const float* __restrict__ W2, const float* __restrict__ b2,
        const float* __restrict__ W1n, float* __restrict__ hout) {
    extern __shared__ float sm[];
    if (blockIdx.x < 256) { spmv1_block(blockIdx.x); return; }
    if (blockIdx.x < 264) { rank_block(blockIdx.x - 256, sm); return; }
    gin_block512(blockIdx.x - 264, g_za, 1.f + eps[0], 0, b1, W2, b2, W1n, hout, g_zb, sm);
}

// ================= K3: spmv2 (0..255) + gin1 (256..767) =================
__global__ __launch_bounds__(512) void k_mid2(
        const float* __restrict__ eps, const int* __restrict__ p,
        const float* __restrict__ b1, const float* __restrict__ W2, const float* __restrict__ b2,
        const float* __restrict__ W1n, float* __restrict__ hout) {
    extern __shared__ float sm[];
    if (blockIdx.x < 256) { spmv2_block(blockIdx.x); return; }
    int cut = (512 * p[0]) / 100;
    gin_block512(blockIdx.x - 256, g_zb, 1.f + eps[1], cut, b1, W2, b2, W1n, hout, g_za, sm);
}

// ================= K4: gin2 (512 blocks) =================
__global__ __launch_bounds__(512) void k_gin2(
        const float* __restrict__ eps, const int* __restrict__ p,
        const float* __restrict__ b1, const float* __restrict__ W2, const float* __restrict__ b2,
        float* __restrict__ hout) {
    extern __shared__ float sm[];
    int cut = (512 * p[0] * 2) / 100;
    gin_block512(blockIdx.x, g_za, 1.f + eps[2], cut, b1, W2, b2, nullptr, hout, nullptr, sm);
}

// ================= K5: readout partial sums =================
__global__ void k_out1(const float* __restrict__ X) {
    int b = blockIdx.x >> 4, seg = blockIdx.x & 15;
    int c = threadIdx.x;
    int n0 = seg * 32;
    float a0 = 0.f, a1 = 0.f, a2 = 0.f, a3 = 0.f;
    if (c < 128) {
        const float* base = X + ((size_t)b * 512 + n0) * 128 + c;
        #pragma unroll 8
        for (int n = 0; n < 32; n += 4) {
            a0 += base[n * 128]; a1 += base[(n + 1) * 128];
            a2 += base[(n + 2) * 128]; a3 += base[(n + 3) * 128];
        }
    } else {
        int l = (c - 128) >> 6, cc = (c - 128) & 63;
        const float* base = g_h[l] + ((size_t)b * 512 + n0) * 64 + cc;
        #pragma unroll 8
        for (int n = 0; n < 32; n += 4) {
            a0 += base[n * 64]; a1 += base[(n + 1) * 64];
            a2 += base[(n + 2) * 64]; a3 += base[(n + 3) * 64];
        }
    }
    g_part[blockIdx.x * 320 + c] = (a0 + a1) + (a2 + a3);
}

// ================= K6: combine + GEMV (0..7) + loss (8) =================
__global__ void k_out2(const float* __restrict__ oW, const float* __restrict__ ob,
                       float* __restrict__ out) {
    if (blockIdx.x == 8) {
        __shared__ float red[256];
        int t = threadIdx.x;
        if (t < 256) {
            float a0 = 0.f, a1 = 0.f, a2 = 0.f, a3 = 0.f;
            for (int i = t * 4; i < BN; i += 1024) {
                a0 += g_term[i]; a1 += g_term[i + 1]; a2 += g_term[i + 2]; a3 += g_term[i + 3];
            }
            red[t] = (a0 + a1) + (a2 + a3);
        }
        __syncthreads();
        for (int s = 128; s > 0; s >>= 1) { if (t < s && t + s < 256) red[t] += red[t + s]; __syncthreads(); }
        if (t == 0) out[80] = red[0];
        return;
    }
    __shared__ float S[320];
    int b = blockIdx.x, c = threadIdx.x;
    float s0 = 0.f;
    #pragma unroll
    for (int seg = 0; seg < 16; seg++) s0 += g_part[(b * 16 + seg) * 320 + c];
    S[c] = s0;
    __syncthreads();
    if (c < 10) {
        float o = ob[c];
        for (int k = 0; k < 320; k++) o = fmaf(S[k], oW[k * 10 + c], o);
        out[b * 10 + c] = o;
    }
}

// ---------------- launch ----------------
extern "C" void kernel_launch(void* const* d_in, const int* in_sizes, int n_in,
                              void* d_out, int out_size) {
    const float* X    = (const float*)d_in[0];
    const float* A    = (const float*)d_in[1];
    const int*   p    = (const int*)  d_in[2];
    const float* cW1  = (const float*)d_in[3];
    const float* cb1  = (const float*)d_in[4];
    const float* cW2  = (const float*)d_in[5];
    const float* cb2  = (const float*)d_in[6];
    const float* wmW1 = (const float*)d_in[7];
    const float* wmb1 = (const float*)d_in[8];
    const float* wmW2 = (const float*)d_in[9];
    const float* wmb2 = (const float*)d_in[10];
    const float* wmW3 = (const float*)d_in[11];
    const float* wmb3 = (const float*)d_in[12];
    const float* fnW1 = (const float*)d_in[13];
    const float* fnb1 = (const float*)d_in[14];
    const float* fnW2 = (const float*)d_in[15];
    const float* fnb2 = (const float*)d_in[16];
    const float* eps  = (const float*)d_in[17];
    const float* g0W1 = (const float*)d_in[18];
    const float* g0b1 = (const float*)d_in[19];
    const float* g0W2 = (const float*)d_in[20];
    const float* g0b2 = (const float*)d_in[21];
    const float* g1W1 = (const float*)d_in[22];
    const float* g1b1 = (const float*)d_in[23];
    const float* g1W2 = (const float*)d_in[24];
    const float* g1b2 = (const float*)d_in[25];
    const float* g2W1 = (const float*)d_in[26];
    const float* g2b1 = (const float*)d_in[27];
    const float* g2W2 = (const float*)d_in[28];
    const float* g2b2 = (const float*)d_in[29];
    const float* oW   = (const float*)d_in[30];
    const float* ob   = (const float*)d_in[31];
    float* out = (float*)d_out;

    float* h0 = nullptr;
    cudaGetSymbolAddress((void**)&h0, g_h);
    float* h1 = h0 + (size_t)BN * HH;
    float* h2 = h0 + (size_t)2 * BN * HH;

    const int SM_PRE = (128 * 64 + 128 * 36 + 32 * 33) * 4;   // 55424
    const int SM_GIN = (4096 + 4096) * 4 + (8 * MAXDEG + 8) * 4
                       + (8 * 66) * 2 * 4 + (8 * 68) * 2 * 4; // ~47k
    cudaFuncSetAttribute(k_pre,  cudaFuncAttributeMaxDynamicSharedMemorySize, SM_PRE);
    cudaFuncSetAttribute(k_mid1, cudaFuncAttributeMaxDynamicSharedMemorySize, SM_GIN);
    cudaFuncSetAttribute(k_mid2, cudaFuncAttributeMaxDynamicSharedMemorySize, SM_GIN);
    cudaFuncSetAttribute(k_gin2, cudaFuncAttributeMaxDynamicSharedMemorySize, SM_GIN);

    k_pre <<<1665, 256, SM_PRE>>>(A, X, cW1, cb1, cW2, cb2, fnW1, fnb1, fnW2, fnb2,
                                  g0W1, wmW1, wmb1, wmW2, wmb2, wmW3, wmb3);
    k_mid1<<<776, 512, SM_GIN>>>(eps, p, g0b1, g0W2, g0b2, g1W1, h0);
    k_mid2<<<768, 512, SM_GIN>>>(eps, p, g1b1, g1W2, g1b2, g2W1, h1);
    k_gin2<<<512, 512, SM_GIN>>>(eps, p, g2b1, g2W2, g2b2, h2);
    k_out1<<<128, 320>>>(X);
    k_out2<<<9, 320>>>(oW, ob, out);
}

// round 13
// speedup vs baseline: 1.0552x; 1.0552x over previous
#include <cuda_runtime.h>
#include <math.h>

#define BB   8
#define NN   512
#define DD   128
#define HH   64
#define FNN  3
#define BN   4096
#define MAXDEG 192

// ---------------- device scratch ----------------
__device__ float  g_wm1;
__device__ float  g_kap[BN];
__device__ float4 g_fp[BN];          // f0,f1,f2 packed
__device__ int    g_rank[BN];
__device__ int    g_cnt[BN];
__device__ int    g_adj[BN][MAXDEG];
__device__ float  g_af[FNN][BN];
__device__ float4 g_gdf[BN * 3];     // per node, per i: (gamma, df, fdf, -)
__device__ float  g_term[BN];
__device__ float  g_h[3][BN * HH];
__device__ float  g_za[BN * HH];
__device__ float  g_zb[BN * HH];
__device__ float  g_part[128 * 256];   // X(128)+h0(64)+h1(64) partials
__device__ float  g_part2[512 * 64];   // h2 per-gin-block partials

// packed dual-fp32 FMA (sm_103a FFMA2)
__device__ __forceinline__ float2 ffma2(float2 a, float2 b, float2 c) {
    union U { float2 f; unsigned long long u; } ua, ub, uc, ud;
    ua.f = a; ub.f = b; uc.f = c;
    asm("fma.rn.f32x2 %0, %1, %2, %3;" : "=l"(ud.u) : "l"(ua.u), "l"(ub.u), "l"(uc.u));
    return ud.f;
}

// ================= K1: adj (0..1023) + node MLPs per-m (1024..1663) + wm1 (1664) =================
__global__ __launch_bounds__(256) void k_pre(
        const float* __restrict__ A, const float* __restrict__ X,
        const float* __restrict__ cW1, const float* __restrict__ cb1,
        const float* __restrict__ cW2, const float* __restrict__ cb2,
        const float* __restrict__ fW1, const float* __restrict__ fb1,
        const float* __restrict__ fW2, const float* __restrict__ fb2,
        const float* __restrict__ z0W1,
        const float* __restrict__ wW1, const float* __restrict__ wb1,
        const float* __restrict__ wW2, const float* __restrict__ wb2,
        const float* __restrict__ wW3, const float* __restrict__ wb3) {
    extern __shared__ float sm[];
    int t = threadIdx.x;
    if (blockIdx.x < 1024) {            // ---- CSR build: 4 rows/block
        int rs = t >> 6;
        int row = blockIdx.x * 4 + rs;
        int tt = t & 63;
        int lane = t & 31;
        int wr = (t >> 5) & 1;
        const float4* A4 = (const float4*)(A + (size_t)row * 512);
        float4 v0 = A4[tt * 2];
        float4 v1 = A4[tt * 2 + 1];
        unsigned flags = (v0.x != 0.f ?   1u : 0u) | (v0.y != 0.f ?   2u : 0u) |
                         (v0.z != 0.f ?   4u : 0u) | (v0.w != 0.f ?   8u : 0u) |
                         (v1.x != 0.f ?  16u : 0u) | (v1.y != 0.f ?  32u : 0u) |
                         (v1.z != 0.f ?  64u : 0u) | (v1.w != 0.f ? 128u : 0u);
        int c = __popc(flags);
        int sc = c;
        #pragma unroll
        for (int o = 1; o < 32; o <<= 1) {
            int n = __shfl_up_sync(0xffffffffu, sc, o);
            if (lane >= o) sc += n;
        }
        __shared__ int wsum[4][2];
        if (lane == 31) wsum[rs][wr] = sc;
        __syncthreads();
        int off = ((wr == 1) ? wsum[rs][0] : 0) + sc - c;
        int col = tt * 8;
        #pragma unroll
        for (int k = 0; k < 8; k++) {
            if ((flags >> k) & 1u) {
                if (off < MAXDEG) g_adj[row][off] = col + k;
                off++;
            }
        }
        if (tt == 63) g_cnt[row] = wsum[rs][0] + wsum[rs][1];
        return;
    }
    if (blockIdx.x == 1664) {           // ---- wm1
        __shared__ float h1[64], h2[32];
        if (t < 64) h1[t] = fmaxf(wW1[t] + wb1[t], 0.f);
        __syncthreads();
        if (t < 32) {
            float s = wb2[t];
            for (int k = 0; k < 64; k++) s = fmaf(h1[k], wW2[k * 32 + t], s);
            h2[t] = fmaxf(s, 0.f);
        }
        __syncthreads();
        if (t == 0) {
            float s = wb3[0];
            for (int k = 0; k < 32; k++) s = fmaf(h2[k], wW3[k], s);
            g_wm1 = 1.f / (1.f + expf(-s));
        }
        return;
    }
    // ---- node MLP: one (m, tile) per block
    int mb = blockIdx.x - 1024;
    int m = mb >> 7;
    int tile = mb & 127;
    float* sW = sm;
    float* xT = sW + 128 * 64;
    float* sP = xT + 128 * 36;
    int row0 = tile * 32;
    const float* W1 = (m == 0) ? cW1 : (m < 4 ? fW1 + (m - 1) * 8192 : z0W1);
    for (int i = t; i < 2048; i += 256) ((float4*)sW)[i] = ((const float4*)W1)[i];
    #pragma unroll
    for (int k = 0; k < 4; k++) {
        int i = t + k * 256;
        float4 v = ((const float4*)(X + (size_t)row0 * 128))[i];
        int li = i * 4;
        int r = li >> 7, d = li & 127;
        xT[(d + 0) * 36 + r] = v.x;
        xT[(d + 1) * 36 + r] = v.y;
        xT[(d + 2) * 36 + r] = v.z;
        xT[(d + 3) * 36 + r] = v.w;
    }
    __syncthreads();
    int hp = t & 31, rq = t >> 5;
    float2 a00 = make_float2(0.f, 0.f), a01 = a00, a10 = a00, a11 = a00;
    #pragma unroll 4
    for (int d = 0; d < 128; d++) {
        float2 wv = *(const float2*)&sW[d * 64 + hp * 2];
        float4 xv = *(const float4*)&xT[d * 36 + rq * 4];
        float2 x01 = make_float2(xv.x, xv.y), x23 = make_float2(xv.z, xv.w);
        float2 w0 = make_float2(wv.x, wv.x), w1 = make_float2(wv.y, wv.y);
        a00 = ffma2(x01, w0, a00); a01 = ffma2(x23, w0, a01);
        a10 = ffma2(x01, w1, a10); a11 = ffma2(x23, w1, a11);
    }
    int rb = rq * 4;
    if (m < 4) {
        const float* b1 = (m == 0) ? cb1 : fb1 + (m - 1) * 64;
        const float* W2 = (m == 0) ? cW2 : fW2 + (m - 1) * 64;
        float b10 = b1[hp * 2], b11 = b1[hp * 2 + 1];
        float w20 = W2[hp * 2], w21 = W2[hp * 2 + 1];
        sP[(rb + 0) * 33 + hp] = fmaxf(a00.x + b10, 0.f) * w20 + fmaxf(a10.x + b11, 0.f) * w21;
        sP[(rb + 1) * 33 + hp] = fmaxf(a00.y + b10, 0.f) * w20 + fmaxf(a10.y + b11, 0.f) * w21;
        sP[(rb + 2) * 33 + hp] = fmaxf(a01.x + b10, 0.f) * w20 + fmaxf(a11.x + b11, 0.f) * w21;
        sP[(rb + 3) * 33 + hp] = fmaxf(a01.y + b10, 0.f) * w20 + fmaxf(a11.y + b11, 0.f) * w21;
        __syncthreads();
        if (t < 32) {
            float s = (m == 0) ? cb2[0] : fb2[m - 1];
            const float* pr = &sP[t * 33];
            #pragma unroll
            for (int k = 0; k < 32; k++) s += pr[k];
            float v = 1.f / (1.f + expf(-s));
            if (m == 0) g_kap[row0 + t] = v;
            else ((float*)&g_fp[row0 + t])[m - 1] = v;
        }
    } else {
        *(float2*)&g_za[(size_t)(row0 + rb + 0) * 64 + hp * 2] = make_float2(a00.x, a10.x);
        *(float2*)&g_za[(size_t)(row0 + rb + 1) * 64 + hp * 2] = make_float2(a00.y, a10.y);
        *(float2*)&g_za[(size_t)(row0 + rb + 2) * 64 + hp * 2] = make_float2(a01.x, a11.x);
        *(float2*)&g_za[(size_t)(row0 + rb + 3) * 64 + hp * 2] = make_float2(a01.y, a11.y);
    }
}

// ================= helpers (512-thread kernels) =================
__device__ __forceinline__ void spmv1_block(int blk) {
    int row = blk * 16 + (threadIdx.x >> 5);
    int lane = threadIdx.x & 31;
    int base = row & ~511;
    int cnt = min(g_cnt[row], MAXDEG);
    float af[FNN] = {0, 0, 0}, aq[FNN] = {0, 0, 0};
    for (int n = lane; n < cnt; n += 32) {
        int gc = base + g_adj[row][n];
        float4 fv = g_fp[gc];
        af[0] += fv.x; aq[0] += fv.x * fv.x;
        af[1] += fv.y; aq[1] += fv.y * fv.y;
        af[2] += fv.z; aq[2] += fv.z * fv.z;
    }
    #pragma unroll
    for (int i = 0; i < FNN; i++) {
        #pragma unroll
        for (int o = 16; o > 0; o >>= 1) {
            af[i] += __shfl_down_sync(0xffffffffu, af[i], o);
            aq[i] += __shfl_down_sync(0xffffffffu, aq[i], o);
        }
    }
    if (lane == 0) {
        float w1 = g_wm1;
        float degw = w1 * (float)cnt;
        float4 fr = g_fp[row];
        const float fa[3] = {fr.x, fr.y, fr.z};
        #pragma unroll
        for (int i = 0; i < FNN; i++) {
            float f = fa[i];
            float wf = w1 * af[i];
            float gamma = 0.5f * (f * f * degw - 2.f * f * wf + w1 * aq[i]);
            float df = f * degw - wf;
            g_af[i][row] = af[i];
            g_gdf[row * 3 + i] = make_float4(gamma, df, f * df, 0.f);
        }
    }
}

__device__ __forceinline__ void spmv2_block(int blk) {
    int row = blk * 16 + (threadIdx.x >> 5);
    int lane = threadIdx.x & 31;
    int base = row & ~511;
    int cnt = min(g_cnt[row], MAXDEG);
    float ag[FNN] = {0, 0, 0}, ad[FNN] = {0, 0, 0}, afd[FNN] = {0, 0, 0};
    for (int n = lane; n < cnt; n += 32) {
        int gc = base + g_adj[row][n];
        #pragma unroll
        for (int i = 0; i < FNN; i++) {
            float4 v = g_gdf[gc * 3 + i];
            ag[i] += v.x; ad[i] += v.y; afd[i] += v.z;
        }
    }
    #pragma unroll
    for (int i = 0; i < FNN; i++) {
        #pragma unroll
        for (int o = 16; o > 0; o >>= 1) {
            ag[i]  += __shfl_down_sync(0xffffffffu, ag[i], o);
            ad[i]  += __shfl_down_sync(0xffffffffu, ad[i], o);
            afd[i] += __shfl_down_sync(0xffffffffu, afd[i], o);
        }
    }
    if (lane == 0) {
        float w1 = g_wm1;
        float kap = g_kap[row];
        float degw = w1 * (float)cnt;
        float term = -3.f * kap;
        float4 fr = g_fp[row];
        const float fa[3] = {fr.x, fr.y, fr.z};
        #pragma unroll
        for (int i = 0; i < FNN; i++) {
            float4 gv = g_gdf[row * 3 + i];
            float f = fa[i];
            float gamma = gv.x, df = gv.y;
            float wf = w1 * g_af[i][row];
            float dgamma = gamma * degw - w1 * ag[i];
            float gfd = 0.5f * (f * df * degw - f * w1 * ad[i]
                                - df * wf + w1 * afd[i]);
            float gamma2 = 0.5f * dgamma - gfd;
            term += fmaxf(kap * gamma - gamma2, 0.f);
        }
        g_term[row] = term;
    }
}

__device__ __forceinline__ void rank_block(int b, float* sv) {
    int t = threadIdx.x;
    sv[t] = g_kap[b * 512 + t];
    __syncthreads();
    float vi = sv[t];
    int c = 0;
    #pragma unroll 8
    for (int j = 0; j < 512; j++) {
        float vj = sv[j];
        c += (vj > vi) || (vj == vi && j < t);
    }
    g_rank[b * 512 + t] = c;
}

// ---- GIN: 8 rows/block, 512 threads; warp=(row, neighbor parity); predicated gather ----
__device__ __forceinline__ void gin_block512(int blk, const float* __restrict__ zin,
                                             float c1, int cut,
                                             const float* __restrict__ b1,
                                             const float* __restrict__ W2, const float* __restrict__ b2,
                                             const float* __restrict__ W1n,
                                             float* __restrict__ hout, float* __restrict__ znext,
                                             bool h2part, float* sm) {
    float* sW2  = sm;                       // 64*64
    float* sW1n = sW2 + 4096;               // 64*64
    float* sPa  = sW1n + 4096;              // 8*66
    float* sPb  = sPa + 8 * 66;             // 8*66
    float* sU   = sPb + 8 * 66;             // 8*68
    float* sH   = sU + 8 * 68;              // 8*68
    int t = threadIdx.x;
    int wr = t >> 5, lane = t & 31;
    int row0 = blk * 8;
    // stage weights (all threads, no barrier needed before gather)
    for (int i = t; i < 1024; i += 512) ((float4*)sW2)[i] = ((const float4*)W2)[i];
    if (W1n) for (int i = t; i < 1024; i += 512) ((float4*)sW1n)[i] = ((const float4*)W1n)[i];
    // gather: warp (r, half) takes neighbors n ≡ half (mod 2), predicated on rank
    int r = wr & 7, half = wr >> 3;
    int row = row0 + r;
    {
        int base = row & ~511;
        int cnt = min(g_cnt[row], MAXDEG);
        float2 a = make_float2(0.f, 0.f);
        bool alive = (cut == 0) || (g_rank[row] >= cut);
        if (alive) {
            const int* adjr = g_adj[row];
            int n = half;
            for (; n + 6 < cnt; n += 8) {
                int i0 = base + adjr[n];
                int i1 = base + adjr[n + 2];
                int i2 = base + adjr[n + 4];
                int i3 = base + adjr[n + 6];
                bool p0 = (cut == 0) || (g_rank[i0] >= cut);
                bool p1 = (cut == 0) || (g_rank[i1] >= cut);
                bool p2 = (cut == 0) || (g_rank[i2] >= cut);
                bool p3 = (cut == 0) || (g_rank[i3] >= cut);
                float2 v0 = *(const float2*)&zin[(size_t)i0 * 64 + lane * 2];
                float2 v1 = *(const float2*)&zin[(size_t)i1 * 64 + lane * 2];
                float2 v2 = *(const float2*)&zin[(size_t)i2 * 64 + lane * 2];
                float2 v3 = *(const float2*)&zin[(size_t)i3 * 64 + lane * 2];
                if (p0) { a.x += v0.x; a.y += v0.y; }
                if (p1) { a.x += v1.x; a.y += v1.y; }
                if (p2) { a.x += v2.x; a.y += v2.y; }
                if (p3) { a.x += v3.x; a.y += v3.y; }
            }
            for (; n < cnt; n += 2) {
                int i0 = base + adjr[n];
                if ((cut == 0) || (g_rank[i0] >= cut)) {
                    float2 v = *(const float2*)&zin[(size_t)i0 * 64 + lane * 2];
                    a.x += v.x; a.y += v.y;
                }
            }
        }
        float* dst = half ? sPb : sPa;
        *(float2*)&dst[r * 66 + lane * 2] = a;
    }
    __syncthreads();
    // combine: warp (r, half) computes u for its 32 dims
    {
        int d = lane + 32 * half;
        float zv = zin[(size_t)row * 64 + d];
        float s = sPa[r * 66 + d] + sPb[r * 66 + d];
        sU[r * 68 + d] = fmaxf(fmaf(c1, zv, s) + b1[d], 0.f);
    }
    __syncthreads();
    // layer 2 (256 threads, float2 weights): thread = (row r2, hid-pair hp)
    if (t < 256) {
        int r2 = t >> 5, hp = t & 31;
        const float* ur = sU + r2 * 68;
        float2 acc = make_float2(0.f, 0.f);
        #pragma unroll 8
        for (int k = 0; k < 64; k++) {
            float uv = ur[k];
            float2 wv = *(const float2*)&sW2[k * 64 + hp * 2];
            acc = ffma2(make_float2(uv, uv), wv, acc);
        }
        float h0v = fmaxf(acc.x + b2[hp * 2], 0.f);
        float h1v = fmaxf(acc.y + b2[hp * 2 + 1], 0.f);
        *(float2*)&hout[(size_t)(row0 + r2) * 64 + hp * 2] = make_float2(h0v, h1v);
        *(float2*)&sH[r2 * 68 + hp * 2] = make_float2(h0v, h1v);
    }
    __syncthreads();
    if (W1n) {                              // znext = h @ W1n
        if (t < 256) {
            int r2 = t >> 5, hp = t & 31;
            const float* hr = sH + r2 * 68;
            float2 acc = make_float2(0.f, 0.f);
            #pragma unroll 8
            for (int k = 0; k < 64; k++) {
                float hv = hr[k];
                float2 wv = *(const float2*)&sW1n[k * 64 + hp * 2];
                acc = ffma2(make_float2(hv, hv), wv, acc);
            }
            *(float2*)&znext[(size_t)(row0 + r2) * 64 + hp * 2] = acc;
        }
    } else if (h2part) {                    // deterministic per-block h2 column partials
        if (t < 64) {
            float s = 0.f;
            #pragma unroll
            for (int rr = 0; rr < 8; rr++) s += sH[rr * 68 + t];
            g_part2[blk * 64 + t] = s;
        }
    }
}

// ================= K2: spmv1 (0..255) + rank (256..263) + gin0 (264..775) =================
__global__ __launch_bounds__(512, 4) void k_mid1(
        const float* __restrict__ eps, const int* __restrict__ p,
        const float* __restrict__ b1, const float* __restrict__ W2, const float* __restrict__ b2,
        const float* __restrict__ W1n, float* __restrict__ hout) {
    extern __shared__ float sm[];
    if (blockIdx.x < 256) { spmv1_block(blockIdx.x); return; }
    if (blockIdx.x < 264) { rank_block(blockIdx.x - 256, sm); return; }
    gin_block512(blockIdx.x - 264, g_za, 1.f + eps[0], 0, b1, W2, b2, W1n, hout, g_zb, false, sm);
}

// ================= K3: spmv2 (0..255) + gin1 (256..767) =================
__global__ __launch_bounds__(512, 4) void k_mid2(
        const float* __restrict__ eps, const int* __restrict__ p,
        const float* __restrict__ b1, const float* __restrict__ W2, const float* __restrict__ b2,
        const float* __restrict__ W1n, float* __restrict__ hout) {
    extern __shared__ float sm[];
    if (blockIdx.x < 256) { spmv2_block(blockIdx.x); return; }
    int cut = (512 * p[0]) / 100;
    gin_block512(blockIdx.x - 256, g_zb, 1.f + eps[1], cut, b1, W2, b2, W1n, hout, g_za, false, sm);
}

// ================= K4: gin2 (0..511) + X/h0/h1 readout partials (512..639) =================
__global__ __launch_bounds__(512, 4) void k_gin2(
        const float* __restrict__ X,
        const float* __restrict__ eps, const int* __restrict__ p,
        const float* __restrict__ b1, const float* __restrict__ W2, const float* __restrict__ b2,
        float* __restrict__ hout) {
    extern __shared__ float sm[];
    if (blockIdx.x < 512) {
        int cut = (512 * p[0] * 2) / 100;
        gin_block512(blockIdx.x, g_za, 1.f + eps[2], cut, b1, W2, b2, nullptr, hout, nullptr, true, sm);
        return;
    }
    // readout partials: 128 blocks, 32 nodes each; c<128: X, 128..191: h0, 192..255: h1
    int blk2 = blockIdx.x - 512;
    int b = blk2 >> 4, seg = blk2 & 15;
    int c = threadIdx.x;
    if (c >= 256) return;
    int n0 = seg * 32;
    float a0 = 0.f, a1 = 0.f, a2 = 0.f, a3 = 0.f;
    if (c < 128) {
        const float* base = X + ((size_t)b * 512 + n0) * 128 + c;
        #pragma unroll 8
        for (int n = 0; n < 32; n += 4) {
            a0 += base[n * 128]; a1 += base[(n + 1) * 128];
            a2 += base[(n + 2) * 128]; a3 += base[(n + 3) * 128];
        }
    } else {
        int l = (c - 128) >> 6, cc = (c - 128) & 63;
        const float* base = g_h[l] + ((size_t)b * 512 + n0) * 64 + cc;
        #pragma unroll 8
        for (int n = 0; n < 32; n += 4) {
            a0 += base[n * 64]; a1 += base[(n + 1) * 64];
            a2 += base[(n + 2) * 64]; a3 += base[(n + 3) * 64];
        }
    }
    g_part[blk2 * 256 + c] = (a0 + a1) + (a2 + a3);
}

// ================= K5: combine + GEMV (0..7) + loss (8) =================
__global__ void k_out2(const float* __restrict__ oW, const float* __restrict__ ob,
                       float* __restrict__ out) {
    if (blockIdx.x == 8) {
        __shared__ float red[256];
        int t = threadIdx.x;
        if (t < 256) {
            float a0 = 0.f, a1 = 0.f, a2 = 0.f, a3 = 0.f;
            for (int i = t * 4; i < BN; i += 1024) {
                a0 += g_term[i]; a1 += g_term[i + 1]; a2 += g_term[i + 2]; a3 += g_term[i + 3];
            }
            red[t] = (a0 + a1) + (a2 + a3);
        }
        __syncthreads();
        for (int s = 128; s > 0; s >>= 1) { if (t < s && t + s < 256) red[t] += red[t + s]; __syncthreads(); }
        if (t == 0) out[80] = red[0];
        return;
    }
    __shared__ float S[320];
    int b = blockIdx.x, c = threadIdx.x;
    if (c < 256) {
        float s0 = 0.f;
        #pragma unroll
        for (int seg = 0; seg < 16; seg++) s0 += g_part[(b * 16 + seg) * 256 + c];
        S[c] = s0;
    } else {
        float s0 = 0.f;
        int cc = c - 256;
        #pragma unroll 8
        for (int j = 0; j < 64; j++) s0 += g_part2[(b * 64 + j) * 64 + cc];
        S[c] = s0;
    }
    __syncthreads();
    if (c < 10) {
        float o = ob[c];
        for (int k = 0; k < 320; k++) o = fmaf(S[k], oW[k * 10 + c], o);
        out[b * 10 + c] = o;
    }
}

// ---------------- launch ----------------
extern "C" void kernel_launch(void* const* d_in, const int* in_sizes, int n_in,
                              void* d_out, int out_size) {
    const float* X    = (const float*)d_in[0];
    const float* A    = (const float*)d_in[1];
    const int*   p    = (const int*)  d_in[2];
    const float* cW1  = (const float*)d_in[3];
    const float* cb1  = (const float*)d_in[4];
    const float* cW2  = (const float*)d_in[5];
    const float* cb2  = (const float*)d_in[6];
    const float* wmW1 = (const float*)d_in[7];
    const float* wmb1 = (const float*)d_in[8];
    const float* wmW2 = (const float*)d_in[9];
    const float* wmb2 = (const float*)d_in[10];
    const float* wmW3 = (const float*)d_in[11];
    const float* wmb3 = (const float*)d_in[12];
    const float* fnW1 = (const float*)d_in[13];
    const float* fnb1 = (const float*)d_in[14];
    const float* fnW2 = (const float*)d_in[15];
    const float* fnb2 = (const float*)d_in[16];
    const float* eps  = (const float*)d_in[17];
    const float* g0W1 = (const float*)d_in[18];
    const float* g0b1 = (const float*)d_in[19];
    const float* g0W2 = (const float*)d_in[20];
    const float* g0b2 = (const float*)d_in[21];
    const float* g1W1 = (const float*)d_in[22];
    const float* g1b1 = (const float*)d_in[23];
    const float* g1W2 = (const float*)d_in[24];
    const float* g1b2 = (const float*)d_in[25];
    const float* g2W1 = (const float*)d_in[26];
    const float* g2b1 = (const float*)d_in[27];
    const float* g2W2 = (const float*)d_in[28];
    const float* g2b2 = (const float*)d_in[29];
    const float* oW   = (const float*)d_in[30];
    const float* ob   = (const float*)d_in[31];
    float* out = (float*)d_out;

    float* h0 = nullptr;
    cudaGetSymbolAddress((void**)&h0, g_h);
    float* h1 = h0 + (size_t)BN * HH;
    float* h2 = h0 + (size_t)2 * BN * HH;

    const int SM_PRE = (128 * 64 + 128 * 36 + 32 * 33) * 4;                      // 55424
    const int SM_GIN = (4096 + 4096 + 8 * 66 * 2 + 8 * 68 * 2) * 4;              // 41344
    cudaFuncSetAttribute(k_pre,  cudaFuncAttributeMaxDynamicSharedMemorySize, SM_PRE);
    cudaFuncSetAttribute(k_mid1, cudaFuncAttributeMaxDynamicSharedMemorySize, SM_GIN);
    cudaFuncSetAttribute(k_mid2, cudaFuncAttributeMaxDynamicSharedMemorySize, SM_GIN);
    cudaFuncSetAttribute(k_gin2, cudaFuncAttributeMaxDynamicSharedMemorySize, SM_GIN);

    k_pre <<<1665, 256, SM_PRE>>>(A, X, cW1, cb1, cW2, cb2, fnW1, fnb1, fnW2, fnb2,
                                  g0W1, wmW1, wmb1, wmW2, wmb2, wmW3, wmb3);
    k_mid1<<<776, 512, SM_GIN>>>(eps, p, g0b1, g0W2, g0b2, g1W1, h0);
    k_mid2<<<768, 512, SM_GIN>>>(eps, p, g1b1, g1W2, g1b2, g2W1, h1);
    k_gin2<<<640, 512, SM_GIN>>>(X, eps, p, g2b1, g2W2, g2b2, h2);
    k_out2<<<9, 320>>>(oW, ob, out);
}